// round 6
// baseline (speedup 1.0000x reference)
#include <cuda_runtime.h>
#include <cuda_bf16.h>
#include <cstdint>

// Problem constants (PairInitOPM: B=1, L=768, sd=384, pd=128)
#define Lq 768
#define SD 384
#define PD 128
#define SD4 (SD / 4)   // 96
#define PD4 (PD / 4)   // 32

// Scratch (allocation-free rule: __device__ globals)
__device__ float g_P[Lq * PD];            // si  (includes bi)
__device__ float g_Q[Lq * PD];            // sj  (includes bj)
__device__ float g_U[Lq * PD];            // zi + bm
__device__ float g_V[Lq * PD];            // zj
__device__ float4 g_Wt4[SD4 * 256];       // Wt4[kb][c] = W[c][4kb..4kb+3], W = [wi;wj]
__device__ float4 g_WmT4[PD4 * 256];      // WmT4[kb][c] = wm[c&127][(c>>7)*128 + 4kb..]

// ---- packed f32x2 helpers (FFMA2: 2 fp32 FMA per instruction) ----
__device__ __forceinline__ uint64_t pk2(float lo, float hi) {
    uint64_t r; asm("mov.b64 %0, {%1, %2};" : "=l"(r) : "f"(lo), "f"(hi)); return r;
}
__device__ __forceinline__ void upk2(uint64_t v, float& lo, float& hi) {
    asm("mov.b64 {%0, %1}, %2;" : "=f"(lo), "=f"(hi) : "l"(v));
}
__device__ __forceinline__ uint64_t fma2(uint64_t a, uint64_t b, uint64_t c) {
    uint64_t d; asm("fma.rn.f32x2 %0, %1, %2, %3;" : "=l"(d) : "l"(a), "l"(b), "l"(c));
    return d;
}

// ---------------------------------------------------------------------------
// Kernel 0: weight transpose (tiny). 128 blocks x 256.
// ---------------------------------------------------------------------------
__global__ __launch_bounds__(256) void k0_transpose(
    const float* __restrict__ wi, const float* __restrict__ wj,
    const float* __restrict__ wm)
{
    int idx = blockIdx.x * 256 + threadIdx.x;
    if (idx < SD4 * 256) {
        int kb = idx >> 8, c = idx & 255;
        const float4* wr4 = (const float4*)((c < PD) ? (wi + c * SD)
                                                     : (wj + (c - PD) * SD));
        g_Wt4[kb * 256 + c] = wr4[kb];
    } else if (idx < (SD4 + PD4) * 256) {
        int j = idx - SD4 * 256;
        int kb = j >> 8, c = j & 255;
        const float4* wr4 = (const float4*)(wm + (c & 127) * (2 * PD) + (c >> 7) * PD);
        g_WmT4[kb * 256 + c] = wr4[kb];
    }
}

// ---------------------------------------------------------------------------
// Kernel 1: TI=6 rows/block -> 128 blocks = one wave.
// Weights: coalesced LDG.128 from transposed layout (no weight SMEM at all).
// s / sisj: LDS.128 broadcast. FMAs: packed f32x2.
// ---------------------------------------------------------------------------
#define TI 6

__global__ __launch_bounds__(256) void k1_proj(
    const float* __restrict__ s,
    const float* __restrict__ bi, const float* __restrict__ bj,
    const float* __restrict__ bm)
{
    __shared__ float4 s_sh4[TI * SD4];   // 9.2 KB
    __shared__ float4 sisj4[TI * 64];    // 6 KB

    const int t  = threadIdx.x;          // output column c = t
    const int i0 = blockIdx.x * TI;

    const float4* __restrict__ S4 = (const float4*)s;
    for (int idx = t; idx < TI * SD4; idx += 256)
        s_sh4[idx] = S4[i0 * SD4 + idx];
    __syncthreads();

    // ---- Phase A: acc[r] = sum_k s[i0+r][k] * W[t][k] ----
    uint64_t acc2[TI];
#pragma unroll
    for (int r = 0; r < TI; r++) acc2[r] = 0ull;

#pragma unroll 4
    for (int kb = 0; kb < SD4; kb++) {
        float4 w4 = g_Wt4[kb * 256 + t];          // coalesced LDG.128 (L2 hit)
        uint64_t wlo = pk2(w4.x, w4.y), whi = pk2(w4.z, w4.w);
#pragma unroll
        for (int r = 0; r < TI; r++) {
            float4 s4 = s_sh4[r * SD4 + kb];      // LDS.128 broadcast
            acc2[r] = fma2(pk2(s4.x, s4.y), wlo, acc2[r]);
            acc2[r] = fma2(pk2(s4.z, s4.w), whi, acc2[r]);
        }
    }

    float acc[TI];
    {
        float b = (t < PD) ? bi[t] : bj[t - PD];
#pragma unroll
        for (int r = 0; r < TI; r++) {
            float lo, hi; upk2(acc2[r], lo, hi);
            acc[r] = lo + hi + b;
        }
    }

    // Publish sisj [TI][256]
    float* sisj = (float*)sisj4;
#pragma unroll
    for (int r = 0; r < TI; r++) sisj[r * 256 + t] = acc[r];
    __syncthreads();

    // ---- Phase B: accz[e] = sum_d sisj[r][which*128+d] * wm[e][which*128+d] ----
    const int which = t >> 7;            // uniform per warp
    const int e     = t & 127;
    uint64_t az2[TI];
#pragma unroll
    for (int r = 0; r < TI; r++) az2[r] = 0ull;

#pragma unroll 4
    for (int kb = 0; kb < PD4; kb++) {
        float4 w4 = g_WmT4[kb * 256 + t];         // coalesced LDG.128
        uint64_t wlo = pk2(w4.x, w4.y), whi = pk2(w4.z, w4.w);
#pragma unroll
        for (int r = 0; r < TI; r++) {
            float4 z4 = sisj4[r * 64 + which * 32 + kb];   // LDS.128 broadcast
            az2[r] = fma2(pk2(z4.x, z4.y), wlo, az2[r]);
            az2[r] = fma2(pk2(z4.z, z4.w), whi, az2[r]);
        }
    }

    const float bmv = bm[e];
#pragma unroll
    for (int r = 0; r < TI; r++) {
        float lo, hi; upk2(az2[r], lo, hi);
        float z = lo + hi;
        int i = i0 + r;
        if (which == 0) {
            g_P[i * PD + e] = acc[r];
            g_U[i * PD + e] = z + bmv;
        } else {
            g_Q[i * PD + e] = acc[r];
            g_V[i * PD + e] = z;
        }
    }
}

// ---------------------------------------------------------------------------
// Kernel 2: z0[i,j,d] = U[i,d] + V[j,d] + P[i,d]*Q[j,d]
// EXACT R3 config (measured 47.3us @ 64.9% DRAM, 40 regs, occ ~65%):
// Block = 8 i x 32 j tile; Q/V staged in smem; streaming float4 stores.
// ---------------------------------------------------------------------------
#define BI 8
#define BJ 32

__global__ __launch_bounds__(256) void k2_outer(float* __restrict__ out)
{
    __shared__ float4 q_sh[BJ * 32];   // 16 KB
    __shared__ float4 v_sh[BJ * 32];   // 16 KB

    const int t  = threadIdx.x;
    const int tx = t & 31;             // d quad: d = 4*tx
    const int ty = t >> 5;             // i within tile (0..7)
    const int i  = blockIdx.x * BI + ty;
    const int j0 = blockIdx.y * BJ;

    const float4* __restrict__ P4 = (const float4*)g_P;
    const float4* __restrict__ Q4 = (const float4*)g_Q;
    const float4* __restrict__ U4 = (const float4*)g_U;
    const float4* __restrict__ V4 = (const float4*)g_V;

#pragma unroll
    for (int m = 0; m < (BJ * 32) / 256; m++) {
        int idx = t + m * 256;
        q_sh[idx] = Q4[j0 * 32 + idx];
        v_sh[idx] = V4[j0 * 32 + idx];
    }

    const float4 p = P4[i * 32 + tx];
    const float4 u = U4[i * 32 + tx];
    __syncthreads();

    float4* out4 = (float4*)out;
    size_t base = ((size_t)i * Lq + j0) * 32 + tx;

#pragma unroll 8
    for (int jj = 0; jj < BJ; jj++) {
        float4 q = q_sh[jj * 32 + tx];     // LDS.128, conflict-free
        float4 v = v_sh[jj * 32 + tx];
        float4 o;
        o.x = fmaf(p.x, q.x, u.x + v.x);
        o.y = fmaf(p.y, q.y, u.y + v.y);
        o.z = fmaf(p.z, q.z, u.z + v.z);
        o.w = fmaf(p.w, q.w, u.w + v.w);
        __stcs(&out4[base + (size_t)jj * 32], o);  // streaming store
    }
}

// ---------------------------------------------------------------------------
extern "C" void kernel_launch(void* const* d_in, const int* in_sizes, int n_in,
                              void* d_out, int out_size)
{
    const float* s  = (const float*)d_in[0];
    const float* wi = (const float*)d_in[1];
    const float* bi = (const float*)d_in[2];
    const float* wj = (const float*)d_in[3];
    const float* bj = (const float*)d_in[4];
    const float* wm = (const float*)d_in[5];
    const float* bm = (const float*)d_in[6];
    float* out = (float*)d_out;

    k0_transpose<<<128, 256>>>(wi, wj, wm);
    k1_proj<<<Lq / TI, 256>>>(s, bi, bj, bm);

    dim3 grid2(Lq / BI, Lq / BJ);
    k2_outer<<<grid2, 256>>>(out);
}

// round 7
// speedup vs baseline: 1.1236x; 1.1236x over previous
#include <cuda_runtime.h>
#include <cuda_bf16.h>
#include <cstdint>

// Problem constants (PairInitOPM: B=1, L=768, sd=384, pd=128)
#define Lq 768
#define SD 384
#define PD 128
#define SD4 (SD / 4)   // 96 float4 per s row
#define PD4 (PD / 4)   // 32 float4 per wm half-row

// Scratch (allocation-free rule: __device__ globals)
__device__ float g_P[Lq * PD];  // si  (includes bi)
__device__ float g_Q[Lq * PD];  // sj  (includes bj)
__device__ float g_U[Lq * PD];  // zi + bm
__device__ float g_V[Lq * PD];  // zj

// ---- cp.async helpers ----
__device__ __forceinline__ void cp_async16(uint32_t dst_smem, const void* src) {
    asm volatile("cp.async.cg.shared.global [%0], [%1], 16;" :: "r"(dst_smem), "l"(src));
}
__device__ __forceinline__ void cp_commit() { asm volatile("cp.async.commit_group;"); }
template <int N>
__device__ __forceinline__ void cp_wait() { asm volatile("cp.async.wait_group %0;" :: "n"(N)); }

// ---------------------------------------------------------------------------
// Kernel 1: TI=6 rows/block -> 128 blocks = one wave.
// Weight tiles (32 k) staged straight from the ORIGINAL layout with
// cp.async.16, double-buffered. Compute: float4 smem reads
//   w: w_sh4[t*9+m]  -> 4 conflict-free wavefronts (pad 9)
//   s: broadcast     -> 1 wavefront
// Dynamic smem: w[2][256*9] + s[TI*96] + sisj[TI*64] float4 = 87 KB.
// ---------------------------------------------------------------------------
#define TI 6
#define WPAD 9                     // float4 per col slot (8 data + 1 pad)
#define WBUF (256 * WPAD)          // float4 per buffer
#define NTA 12                     // phase-A tiles (96 float4-k / 8)
#define NTB 4                      // phase-B tiles (32 float4-k / 8)
#define K1_SMEM_BYTES ((2 * WBUF + TI * SD4 + TI * 64) * 16)

__global__ __launch_bounds__(256) void k1_proj(
    const float* __restrict__ s,
    const float* __restrict__ wi, const float* __restrict__ bi,
    const float* __restrict__ wj, const float* __restrict__ bj,
    const float* __restrict__ wm, const float* __restrict__ bm)
{
    extern __shared__ float4 sm4[];
    float4* w_sh4  = sm4;                        // [2][256*WPAD]
    float4* s_sh4  = sm4 + 2 * WBUF;             // [TI][SD4]
    float4* sisj4  = s_sh4 + TI * SD4;           // [TI][64]

    const int t  = threadIdx.x;                  // output column c = t
    const int i0 = blockIdx.x * TI;
    const uint32_t w_sm = (uint32_t)__cvta_generic_to_shared(w_sh4);

    // Staging role: lanes of 8 cover one row's 8 float4 (coalesced 128B)
    const int sc = t >> 3;                       // base col (0..31), step 32
    const int sm_ = t & 7;                       // float4 index within tile

    // Load s rows (float4, coalesced)
    const float4* __restrict__ S4 = (const float4*)s;
    for (int idx = t; idx < TI * SD4; idx += 256)
        s_sh4[idx] = S4[i0 * SD4 + idx];

    float acc[TI];
#pragma unroll
    for (int r = 0; r < TI; r++) acc[r] = 0.f;

    // ---------------- Phase A ----------------
    auto stageA = [&](int tile, int b) {
        const int kq0 = tile * 8;                // float4-k offset
#pragma unroll
        for (int it = 0; it < 8; it++) {
            int c = sc + 32 * it;
            const float* wr = (c < PD) ? (wi + c * SD) : (wj + (c - PD) * SD);
            cp_async16(w_sm + (uint32_t)((b * WBUF + c * WPAD + sm_) * 16),
                       (const float4*)wr + kq0 + sm_);
        }
        cp_commit();
    };

    stageA(0, 0);
    for (int tile = 0; tile < NTA; tile++) {
        if (tile + 1 < NTA) { stageA(tile + 1, (tile + 1) & 1); cp_wait<1>(); }
        else                { cp_wait<0>(); }
        __syncthreads();                          // tile visible (covers s on t0)
        const float4* wb = w_sh4 + (tile & 1) * WBUF;
        const int kq0 = tile * 8;
#pragma unroll
        for (int m = 0; m < 8; m++) {
            float4 w4 = wb[t * WPAD + m];         // 4 conflict-free wavefronts
#pragma unroll
            for (int r = 0; r < TI; r++) {
                float4 s4 = s_sh4[r * SD4 + kq0 + m];   // broadcast
                acc[r] = fmaf(s4.x, w4.x, acc[r]);
                acc[r] = fmaf(s4.y, w4.y, acc[r]);
                acc[r] = fmaf(s4.z, w4.z, acc[r]);
                acc[r] = fmaf(s4.w, w4.w, acc[r]);
            }
        }
        __syncthreads();                          // buffer reusable
    }

    {
        float b = (t < PD) ? bi[t] : bj[t - PD];
#pragma unroll
        for (int r = 0; r < TI; r++) acc[r] += b;
    }

    // Publish sisj [TI][256 floats] = [TI][64 float4]
    float* sisj = (float*)sisj4;
#pragma unroll
    for (int r = 0; r < TI; r++) sisj[r * 256 + t] = acc[r];

    // ---------------- Phase B ----------------
    const int which = t >> 7;                     // uniform per warp
    const int e     = t & 127;
    float az[TI];
#pragma unroll
    for (int r = 0; r < TI; r++) az[r] = 0.f;

    auto stageB = [&](int tile, int b) {
        const int kq0 = tile * 8;
#pragma unroll
        for (int it = 0; it < 8; it++) {
            int c = sc + 32 * it;
            const float* wr = wm + (c & 127) * (2 * PD) + (c >> 7) * PD;
            cp_async16(w_sm + (uint32_t)((b * WBUF + c * WPAD + sm_) * 16),
                       (const float4*)wr + kq0 + sm_);
        }
        cp_commit();
    };

    stageB(0, 0);
    for (int tile = 0; tile < NTB; tile++) {
        if (tile + 1 < NTB) { stageB(tile + 1, (tile + 1) & 1); cp_wait<1>(); }
        else                { cp_wait<0>(); }
        __syncthreads();                          // also publishes sisj (tile 0)
        const float4* wb = w_sh4 + (tile & 1) * WBUF;
        const int kq0 = tile * 8;
#pragma unroll
        for (int m = 0; m < 8; m++) {
            float4 w4 = wb[t * WPAD + m];
#pragma unroll
            for (int r = 0; r < TI; r++) {
                float4 z4 = sisj4[r * 64 + which * 32 + kq0 + m];  // broadcast
                az[r] = fmaf(z4.x, w4.x, az[r]);
                az[r] = fmaf(z4.y, w4.y, az[r]);
                az[r] = fmaf(z4.z, w4.z, az[r]);
                az[r] = fmaf(z4.w, w4.w, az[r]);
            }
        }
        __syncthreads();
    }

    const float bmv = bm[e];
#pragma unroll
    for (int r = 0; r < TI; r++) {
        int i = i0 + r;
        if (which == 0) {
            g_P[i * PD + e] = acc[r];
            g_U[i * PD + e] = az[r] + bmv;
        } else {
            g_Q[i * PD + e] = acc[r];
            g_V[i * PD + e] = az[r];
        }
    }
}

// ---------------------------------------------------------------------------
// Kernel 2: z0[i,j,d] = U[i,d] + V[j,d] + P[i,d]*Q[j,d]
// EXACT R3 config (measured 47.3us @ 64.9% DRAM across 3 rounds).
// ---------------------------------------------------------------------------
#define BI 8
#define BJ 32

__global__ __launch_bounds__(256) void k2_outer(float* __restrict__ out)
{
    __shared__ float4 q_sh[BJ * 32];   // 16 KB
    __shared__ float4 v_sh[BJ * 32];   // 16 KB

    const int t  = threadIdx.x;
    const int tx = t & 31;             // d quad: d = 4*tx
    const int ty = t >> 5;             // i within tile (0..7)
    const int i  = blockIdx.x * BI + ty;
    const int j0 = blockIdx.y * BJ;

    const float4* __restrict__ P4 = (const float4*)g_P;
    const float4* __restrict__ Q4 = (const float4*)g_Q;
    const float4* __restrict__ U4 = (const float4*)g_U;
    const float4* __restrict__ V4 = (const float4*)g_V;

#pragma unroll
    for (int m = 0; m < (BJ * 32) / 256; m++) {
        int idx = t + m * 256;
        q_sh[idx] = Q4[j0 * 32 + idx];
        v_sh[idx] = V4[j0 * 32 + idx];
    }

    const float4 p = P4[i * 32 + tx];
    const float4 u = U4[i * 32 + tx];
    __syncthreads();

    float4* out4 = (float4*)out;
    size_t base = ((size_t)i * Lq + j0) * 32 + tx;

#pragma unroll 8
    for (int jj = 0; jj < BJ; jj++) {
        float4 q = q_sh[jj * 32 + tx];     // LDS.128, conflict-free
        float4 v = v_sh[jj * 32 + tx];
        float4 o;
        o.x = fmaf(p.x, q.x, u.x + v.x);
        o.y = fmaf(p.y, q.y, u.y + v.y);
        o.z = fmaf(p.z, q.z, u.z + v.z);
        o.w = fmaf(p.w, q.w, u.w + v.w);
        __stcs(&out4[base + (size_t)jj * 32], o);  // streaming store
    }
}

// ---------------------------------------------------------------------------
extern "C" void kernel_launch(void* const* d_in, const int* in_sizes, int n_in,
                              void* d_out, int out_size)
{
    const float* s  = (const float*)d_in[0];
    const float* wi = (const float*)d_in[1];
    const float* bi = (const float*)d_in[2];
    const float* wj = (const float*)d_in[3];
    const float* bj = (const float*)d_in[4];
    const float* wm = (const float*)d_in[5];
    const float* bm = (const float*)d_in[6];
    float* out = (float*)d_out;

    // Idempotent, deterministic, not an allocation: raise dynamic-smem cap.
    cudaFuncSetAttribute(k1_proj, cudaFuncAttributeMaxDynamicSharedMemorySize,
                         K1_SMEM_BYTES);

    k1_proj<<<Lq / TI, 256, K1_SMEM_BYTES>>>(s, wi, bi, wj, bj, wm, bm);

    dim3 grid2(Lq / BI, Lq / BJ);
    k2_outer<<<grid2, 256>>>(out);
}